// round 8
// baseline (speedup 1.0000x reference)
#include <cuda_runtime.h>
#include <cuda_bf16.h>

#define N_STEPS   256
#define N_LORS    65536
#define IMG_ELEMS (128*128*128)

#define RCP_VOX (1.0f / 2.34375f)
#define VOX     2.34375f

// div.rn(x, VOX) via correctly-rounded reciprocal + one Markstein FMA step:
// matches IEEE division to <1e-9/coord flip probability (see r6/r7 notes).
__device__ __forceinline__ float div_vox(float x) {
    float q = __fmul_rn(x, RCP_VOX);
    q = __fmaf_rn(__fmaf_rn(-VOX, q, x), RCP_VOX, q);
    return q;
}

// ---------------------------------------------------------------------------
// Trace kernel: warp-per-LOR, lane = consecutive step within 32-step chunk.
//   Forward: 8 independent gathers.
//   Backward: runs grouped by 16B-aligned z-QUAD (4 consecutive voxels);
//             one float4 red.global per quad instead of one fp32 red per
//             voxel-run -> ~25% fewer atomic lanes (z-moves merge for free).
// ---------------------------------------------------------------------------
__global__ __launch_bounds__(256)
void trace_kernel(const float* __restrict__ img,
                  const float* __restrict__ xl,
                  const float* __restrict__ yl,
                  const float* __restrict__ zl,
                  float* __restrict__ acc) {
    const int warp = blockIdx.x * (blockDim.x >> 5) + (threadIdx.x >> 5);
    const int lane = threadIdx.x & 31;
    const int set  = warp >> 16;          // 0,1,2
    const int lor  = warp & (N_LORS - 1);

    const float* lors = (set == 0) ? xl : (set == 1) ? yl : zl;
    const float* L = lors + 7 * lor;

    const float p1x = __ldg(L + 0), p1y = __ldg(L + 1), p1z = __ldg(L + 2);
    const float dx = __fadd_rn(__ldg(L + 3), -p1x);
    const float dy = __fadd_rn(__ldg(L + 4), -p1y);
    const float dz = __fadd_rn(__ldg(L + 5), -p1z);
    const float meas = __ldg(L + 6);
    const float seg = sqrtf(dx*dx + dy*dy + dz*dz) * (1.0f / N_STEPS);

    int flats[8];

    // exact: all t are multiples of 2^-9
    float t = ((float)lane + 0.5f) * (1.0f / N_STEPS);

    #pragma unroll
    for (int it = 0; it < 8; it++) {
        const float px = __fadd_rn(p1x, __fmul_rn(t, dx));
        const float py = __fadd_rn(p1y, __fmul_rn(t, dy));
        const float pz = __fadd_rn(p1z, __fmul_rn(t, dz));
        const int ix = __float2int_rd(div_vox(__fadd_rn(px, 150.0f)));
        const int iy = __float2int_rd(div_vox(__fadd_rn(py, 150.0f)));
        const int iz = __float2int_rd(div_vox(__fadd_rn(pz, 150.0f)));
        const bool inb = ((unsigned)ix < 128u) & ((unsigned)iy < 128u) &
                         ((unsigned)iz < 128u);
        flats[it] = inb ? (((ix << 7) + iy) << 7) + iz : -1;
        t = __fadd_rn(t, 0.125f);
    }

    // ---- forward projection: 8 independent gathers ----
    float s = 0.f;
    #pragma unroll
    for (int it = 0; it < 8; it++) {
        const int f = flats[it];
        s += (f >= 0) ? __ldg(img + f) : 0.f;
    }

    #pragma unroll
    for (int o = 16; o > 0; o >>= 1)
        s += __shfl_xor_sync(0xffffffffu, s, o);

    const float proj = s * seg;
    const float w = meas / (proj + 1e-8f) * seg;   // ratio * seg

    // ---- backprojection: one float4 atomic per contiguous same-QUAD group --
    #pragma unroll
    for (int it = 0; it < 8; it++) {
        const int f = flats[it];
        const int q = f >> 2;                         // quad id (-1 stays -1)
        const int qprev = __shfl_up_sync(0xffffffffu, q, 1);
        const bool qhead = (lane == 0) || (q != qprev);
        const unsigned hb = __ballot_sync(0xffffffffu, qhead);
        const int slot = f & 3;
        const unsigned b0 = __ballot_sync(0xffffffffu, slot == 0);
        const unsigned b1 = __ballot_sync(0xffffffffu, slot == 1);
        const unsigned b2 = __ballot_sync(0xffffffffu, slot == 2);
        if (qhead && f >= 0) {
            const unsigned after = (hb >> lane) >> 1;     // heads after me
            const int len = after ? __ffs(after) : (32 - lane);
            // members: lanes [lane, lane+len) — all have my q (out-of-bounds
            // lanes have q=-1 and can never be in a valid-q group)
            const unsigned members =
                ((len == 32) ? 0xffffffffu : ((1u << len) - 1u)) << lane;
            float4 v;
            v.x = w * (float)__popc(b0 & members);
            v.y = w * (float)__popc(b1 & members);
            v.z = w * (float)__popc(b2 & members);
            v.w = w * (float)__popc(~(b0 | b1 | b2) & members);
            atomicAdd((float4*)(acc + (q << 2)), v);  // 16B-aligned, +0 adds exact
        }
    }
}

// ---------------------------------------------------------------------------
// Finalize: out = image / (eff + eps) * acc   (in-place on d_out)
// ---------------------------------------------------------------------------
__global__ void finalize_kernel(const float4* __restrict__ img,
                                const float4* __restrict__ eff,
                                float4* __restrict__ out) {
    int i = blockIdx.x * blockDim.x + threadIdx.x;
    float4 a = img[i], e = eff[i], o = out[i];
    o.x = a.x / (e.x + 1e-8f) * o.x;
    o.y = a.y / (e.y + 1e-8f) * o.y;
    o.z = a.z / (e.z + 1e-8f) * o.z;
    o.w = a.w / (e.w + 1e-8f) * o.w;
    out[i] = o;
}

extern "C" void kernel_launch(void* const* d_in, const int* in_sizes, int n_in,
                              void* d_out, int out_size) {
    const float* image = (const float*)d_in[0];
    const float* eff   = (const float*)d_in[1];
    const float* xl    = (const float*)d_in[2];
    const float* yl    = (const float*)d_in[3];
    const float* zl    = (const float*)d_in[4];
    float* out = (float*)d_out;

    cudaMemsetAsync(out, 0, IMG_ELEMS * sizeof(float), 0);

    const int total_warps = 3 * N_LORS;          // one warp per LOR
    trace_kernel<<<total_warps / 8, 256>>>(image, xl, yl, zl, out);

    finalize_kernel<<<IMG_ELEMS / 4 / 256, 256>>>((const float4*)image,
                                                  (const float4*)eff,
                                                  (float4*)out);
}

// round 9
// speedup vs baseline: 1.2426x; 1.2426x over previous
#include <cuda_runtime.h>
#include <cuda_bf16.h>

#define N_STEPS   256
#define N_LORS    65536
#define IMG_ELEMS (128*128*128)

#define RCP_VOX (1.0f / 2.34375f)
#define VOX     2.34375f

// Image and accumulator in sector-tiled (2x2x2 cube) layout:
// one 32B sector = one 2x2x2 voxel cube (4.69mm)^3.
__device__ float g_img_cube[IMG_ELEMS];
__device__ float g_acc_cube[IMG_ELEMS];

__device__ __forceinline__ int cube_flat(int ix, int iy, int iz) {
    const int c = (((ix >> 1) << 6) + (iy >> 1)) * 64 + (iz >> 1);
    return (c << 3) + ((ix & 1) << 2) + ((iy & 1) << 1) + (iz & 1);
}

// div.rn(x, VOX) via correctly-rounded reciprocal + one Markstein FMA step:
// matches IEEE division (flip probability <1e-9/coord; see r6/r7 notes).
__device__ __forceinline__ float div_vox(float x) {
    float q = __fmul_rn(x, RCP_VOX);
    q = __fmaf_rn(__fmaf_rn(-VOX, q, x), RCP_VOX, q);
    return q;
}

// ---------------------------------------------------------------------------
// Kernel 1: remap image -> cube layout, zero accumulator
// ---------------------------------------------------------------------------
__global__ void remap_kernel(const float* __restrict__ img) {
    const int i = blockIdx.x * blockDim.x + threadIdx.x;   // linear voxel id
    const int ix = i >> 14, iy = (i >> 7) & 127, iz = i & 127;
    g_img_cube[cube_flat(ix, iy, iz)] = img[i];
    g_acc_cube[i] = 0.f;
}

// ---------------------------------------------------------------------------
// Kernel 2: warp-per-LOR, lane = consecutive step within each 32-step chunk.
//   Index math bit-exact with jax (separate mul/add, CR division).
//   Forward: 8 independent gathers; cube layout keeps a warp-load's lanes in
//            ~5 sectors for ANY line direction.
//   Backward: one scalar 4B RED per contiguous same-voxel run (byte-minimal,
//            per r8's finding); neighboring runs share sectors in cube layout.
// ---------------------------------------------------------------------------
__global__ __launch_bounds__(256)
void trace_kernel(const float* __restrict__ xl,
                  const float* __restrict__ yl,
                  const float* __restrict__ zl) {
    const int warp = blockIdx.x * (blockDim.x >> 5) + (threadIdx.x >> 5);
    const int lane = threadIdx.x & 31;
    const int set  = warp >> 16;          // 0,1,2
    const int lor  = warp & (N_LORS - 1);

    const float* lors = (set == 0) ? xl : (set == 1) ? yl : zl;
    const float* L = lors + 7 * lor;

    const float p1x = __ldg(L + 0), p1y = __ldg(L + 1), p1z = __ldg(L + 2);
    const float dx = __fadd_rn(__ldg(L + 3), -p1x);
    const float dy = __fadd_rn(__ldg(L + 4), -p1y);
    const float dz = __fadd_rn(__ldg(L + 5), -p1z);
    const float meas = __ldg(L + 6);
    const float seg = sqrtf(dx*dx + dy*dy + dz*dz) * (1.0f / N_STEPS);

    int flats[8];

    // exact: all t are multiples of 2^-9
    float t = ((float)lane + 0.5f) * (1.0f / N_STEPS);

    #pragma unroll
    for (int it = 0; it < 8; it++) {
        const float px = __fadd_rn(p1x, __fmul_rn(t, dx));
        const float py = __fadd_rn(p1y, __fmul_rn(t, dy));
        const float pz = __fadd_rn(p1z, __fmul_rn(t, dz));
        const int ix = __float2int_rd(div_vox(__fadd_rn(px, 150.0f)));
        const int iy = __float2int_rd(div_vox(__fadd_rn(py, 150.0f)));
        const int iz = __float2int_rd(div_vox(__fadd_rn(pz, 150.0f)));
        const bool inb = ((unsigned)ix < 128u) & ((unsigned)iy < 128u) &
                         ((unsigned)iz < 128u);
        flats[it] = inb ? cube_flat(ix, iy, iz) : -1;
        t = __fadd_rn(t, 0.125f);
    }

    // ---- forward projection: 8 independent gathers ----
    float s = 0.f;
    #pragma unroll
    for (int it = 0; it < 8; it++) {
        const int f = flats[it];
        s += (f >= 0) ? __ldg(g_img_cube + f) : 0.f;
    }

    #pragma unroll
    for (int o = 16; o > 0; o >>= 1)
        s += __shfl_xor_sync(0xffffffffu, s, o);

    const float proj = s * seg;
    const float w = meas / (proj + 1e-8f) * seg;   // ratio * seg

    // ---- backprojection: one scalar atomic per contiguous same-voxel run --
    #pragma unroll
    for (int it = 0; it < 8; it++) {
        const int f = flats[it];
        const int fprev = __shfl_up_sync(0xffffffffu, f, 1);
        const bool head = (lane == 0) || (f != fprev);
        const unsigned b = __ballot_sync(0xffffffffu, head);
        if (head && f >= 0) {
            const unsigned rest = (b >> lane) >> 1;   // heads after me
            const int cnt = rest ? __ffs(rest) : (32 - lane);
            atomicAdd(g_acc_cube + f, w * (float)cnt);
        }
    }
}

// ---------------------------------------------------------------------------
// Kernel 3: out = image / (eff + eps) * acc   (gather from cube layout)
// ---------------------------------------------------------------------------
__global__ void finalize_kernel(const float* __restrict__ img,
                                const float* __restrict__ eff,
                                float* __restrict__ out) {
    const int i = blockIdx.x * blockDim.x + threadIdx.x;
    const int ix = i >> 14, iy = (i >> 7) & 127, iz = i & 127;
    const float a = g_acc_cube[cube_flat(ix, iy, iz)];
    out[i] = img[i] / (eff[i] + 1e-8f) * a;
}

extern "C" void kernel_launch(void* const* d_in, const int* in_sizes, int n_in,
                              void* d_out, int out_size) {
    const float* image = (const float*)d_in[0];
    const float* eff   = (const float*)d_in[1];
    const float* xl    = (const float*)d_in[2];
    const float* yl    = (const float*)d_in[3];
    const float* zl    = (const float*)d_in[4];
    float* out = (float*)d_out;

    remap_kernel<<<IMG_ELEMS / 256, 256>>>(image);

    const int total_warps = 3 * N_LORS;          // one warp per LOR
    trace_kernel<<<total_warps / 8, 256>>>(xl, yl, zl);

    finalize_kernel<<<IMG_ELEMS / 256, 256>>>(image, eff, out);
}